// round 12
// baseline (speedup 1.0000x reference)
#include <cuda_runtime.h>

#define N_POINTS 4194304
#define GRIPPER_DEPTH 0.1034f

__global__ void __launch_bounds__(256) contactnet_kernel(
    const float* __restrict__ pts,
    const float* __restrict__ z1,
    const float* __restrict__ z2,
    const float* __restrict__ s,
    const float* __restrict__ w,
    float* __restrict__ out,
    int n)
{
    int i = blockIdx.x * blockDim.x + threadIdx.x;
    if (i >= n) return;

    const int i3 = 3 * i;

    // ---- loads (coalesced; streaming hint, no reuse) ----
    float px = __ldcs(pts + i3 + 0);
    float py = __ldcs(pts + i3 + 1);
    float pz = __ldcs(pts + i3 + 2);

    float ax = __ldcs(z1 + i3 + 0);
    float ay = __ldcs(z1 + i3 + 1);
    float az = __ldcs(z1 + i3 + 2);

    float bx = __ldcs(z2 + i3 + 0);
    float by = __ldcs(z2 + i3 + 1);
    float bz = __ldcs(z2 + i3 + 2);

    float sv = __ldcs(s + i);
    float wv = __ldcs(w + i);

    // ---- x_col = z1 / ||z1|| ----
    float inv1 = rsqrtf(fmaf(ax, ax, fmaf(ay, ay, az * az)));
    float xx = ax * inv1;
    float xy = ay * inv1;
    float xz = az * inv1;

    // ---- z_col = normalize(z2 - (x.z2) x)  (||z2|| divide cancels) ----
    float inner = fmaf(xx, bx, fmaf(xy, by, xz * bz));
    float apx = fmaf(-inner, xx, bx);
    float apy = fmaf(-inner, xy, by);
    float apz = fmaf(-inner, xz, bz);
    float invz = rsqrtf(fmaf(apx, apx, fmaf(apy, apy, apz * apz)));
    float zx = apx * invz;
    float zy = apy * invz;
    float zz = apz * invz;

    // ---- y_col = normalize(cross(z, x)) ----
    float cx = fmaf(zy, xz, -zz * xy);
    float cy = fmaf(zz, xx, -zx * xz);
    float cz = fmaf(zx, xy, -zy * xx);
    float invy = rsqrtf(fmaf(cx, cx, fmaf(cy, cy, cz * cz)));
    float yx = cx * invy;
    float yy = cy * invy;
    float yz = cz * invy;

    // ---- t_col = p + 0.5*w*x - depth*z  (raw w) ----
    float hw = 0.5f * wv;
    float tx = fmaf(hw, xx, fmaf(-GRIPPER_DEPTH, zx, px));
    float ty = fmaf(hw, xy, fmaf(-GRIPPER_DEPTH, zy, py));
    float tz = fmaf(hw, xz, fmaf(-GRIPPER_DEPTH, zz, pz));

    // ---- output layout: points[3N] | grasps[16N] | sigmoid(s)[N] | relu(w)[N] ----
    // points passthrough
    __stcs(out + i3 + 0, px);
    __stcs(out + i3 + 1, py);
    __stcs(out + i3 + 2, pz);

    // grasp 4x4 row-major: rows = components, cols = (x, y, z, t), bottom (0,0,0,1)
    float4* g = reinterpret_cast<float4*>(out + (size_t)3 * n + (size_t)16 * i);
    __stcs(g + 0, make_float4(xx, yx, zx, tx));
    __stcs(g + 1, make_float4(xy, yy, zy, ty));
    __stcs(g + 2, make_float4(xz, yz, zz, tz));
    __stcs(g + 3, make_float4(0.0f, 0.0f, 0.0f, 1.0f));

    // sigmoid(s)
    __stcs(out + (size_t)19 * n + i, 1.0f / (1.0f + expf(-sv)));
    // relu(w)
    __stcs(out + (size_t)20 * n + i, fmaxf(wv, 0.0f));
}

extern "C" void kernel_launch(void* const* d_in, const int* in_sizes, int n_in,
                              void* d_out, int out_size) {
    const float* pts = (const float*)d_in[0];
    const float* z1  = (const float*)d_in[1];
    const float* z2  = (const float*)d_in[2];
    const float* s   = (const float*)d_in[3];
    const float* w   = (const float*)d_in[4];
    float* out = (float*)d_out;

    int n = in_sizes[3];  // element count of s = N
    int threads = 256;
    int blocks = (n + threads - 1) / threads;
    contactnet_kernel<<<blocks, threads>>>(pts, z1, z2, s, w, out, n);
}

// round 13
// speedup vs baseline: 1.0032x; 1.0032x over previous
#include <cuda_runtime.h>

#define N_POINTS 4194304
#define GRIPPER_DEPTH 0.1034f

__global__ void __launch_bounds__(256) contactnet_kernel(
    const float* __restrict__ pts,
    const float* __restrict__ z1,
    const float* __restrict__ z2,
    const float* __restrict__ s,
    const float* __restrict__ w,
    float* __restrict__ out,
    int n)
{
    int i = blockIdx.x * blockDim.x + threadIdx.x;
    if (i >= n) return;

    const int i3 = 3 * i;

    // ---- loads (coalesced; streaming hint, no reuse) ----
    float px = __ldcs(pts + i3 + 0);
    float py = __ldcs(pts + i3 + 1);
    float pz = __ldcs(pts + i3 + 2);

    float ax = __ldcs(z1 + i3 + 0);
    float ay = __ldcs(z1 + i3 + 1);
    float az = __ldcs(z1 + i3 + 2);

    float bx = __ldcs(z2 + i3 + 0);
    float by = __ldcs(z2 + i3 + 1);
    float bz = __ldcs(z2 + i3 + 2);

    float sv = __ldcs(s + i);
    float wv = __ldcs(w + i);

    // ---- x_col = z1 / ||z1|| ----
    float inv1 = rsqrtf(fmaf(ax, ax, fmaf(ay, ay, az * az)));
    float xx = ax * inv1;
    float xy = ay * inv1;
    float xz = az * inv1;

    // ---- z_col = normalize(z2 - (x.z2) x)  (||z2|| divide cancels) ----
    float inner = fmaf(xx, bx, fmaf(xy, by, xz * bz));
    float apx = fmaf(-inner, xx, bx);
    float apy = fmaf(-inner, xy, by);
    float apz = fmaf(-inner, xz, bz);
    float invz = rsqrtf(fmaf(apx, apx, fmaf(apy, apy, apz * apz)));
    float zx = apx * invz;
    float zy = apy * invz;
    float zz = apz * invz;

    // ---- y_col = normalize(cross(z, x)) ----
    float cx = fmaf(zy, xz, -zz * xy);
    float cy = fmaf(zz, xx, -zx * xz);
    float cz = fmaf(zx, xy, -zy * xx);
    float invy = rsqrtf(fmaf(cx, cx, fmaf(cy, cy, cz * cz)));
    float yx = cx * invy;
    float yy = cy * invy;
    float yz = cz * invy;

    // ---- t_col = p + 0.5*w*x - depth*z  (raw w) ----
    float hw = 0.5f * wv;
    float tx = fmaf(hw, xx, fmaf(-GRIPPER_DEPTH, zx, px));
    float ty = fmaf(hw, xy, fmaf(-GRIPPER_DEPTH, zy, py));
    float tz = fmaf(hw, xz, fmaf(-GRIPPER_DEPTH, zz, pz));

    // ---- output layout: points[3N] | grasps[16N] | sigmoid(s)[N] | relu(w)[N] ----
    // points passthrough
    __stcs(out + i3 + 0, px);
    __stcs(out + i3 + 1, py);
    __stcs(out + i3 + 2, pz);

    // grasp 4x4 row-major: rows = components, cols = (x, y, z, t), bottom (0,0,0,1)
    float4* g = reinterpret_cast<float4*>(out + (size_t)3 * n + (size_t)16 * i);
    __stcs(g + 0, make_float4(xx, yx, zx, tx));
    __stcs(g + 1, make_float4(xy, yy, zy, ty));
    __stcs(g + 2, make_float4(xz, yz, zz, tz));
    __stcs(g + 3, make_float4(0.0f, 0.0f, 0.0f, 1.0f));

    // sigmoid(s)
    __stcs(out + (size_t)19 * n + i, 1.0f / (1.0f + expf(-sv)));
    // relu(w)
    __stcs(out + (size_t)20 * n + i, fmaxf(wv, 0.0f));
}

extern "C" void kernel_launch(void* const* d_in, const int* in_sizes, int n_in,
                              void* d_out, int out_size) {
    const float* pts = (const float*)d_in[0];
    const float* z1  = (const float*)d_in[1];
    const float* z2  = (const float*)d_in[2];
    const float* s   = (const float*)d_in[3];
    const float* w   = (const float*)d_in[4];
    float* out = (float*)d_out;

    int n = in_sizes[3];  // element count of s = N
    int threads = 256;
    int blocks = (n + threads - 1) / threads;
    contactnet_kernel<<<blocks, threads>>>(pts, z1, z2, s, w, out, n);
}